// round 2
// baseline (speedup 1.0000x reference)
#include <cuda_runtime.h>
#include <math.h>

// Problem constants
#define Bb 2
#define Ss 2048
#define Dd 1024
#define Hh 16
#define HD 64
#define Mrows (Bb*Ss)          // 4096

// Scratch (device globals; no allocation)
__device__ float g_qkv[(size_t)Mrows * 3 * Dd];   // [4096][3072]
__device__ float g_att[(size_t)Mrows * Dd];       // [4096][1024]

// ---------------------------------------------------------------------------
// SGEMM: C[M,N] = A[M,K] @ B[K,N] + bias[N]
// 128x128 block tile, BK=8, 256 threads, 8x8 per-thread micro-tile.
// Requires M%128==0, N%128==0, K%8==0 (true for all our shapes).
// ---------------------------------------------------------------------------
#define BM 128
#define BN 128
#define BKk 8
#define TM 8
#define TN 8

__global__ __launch_bounds__(256)
void sgemm_bias(const float* __restrict__ A, const float* __restrict__ B,
                const float* __restrict__ bias, float* __restrict__ C,
                int M, int N, int K) {
    __shared__ float As[BKk][BM];   // A tile transposed: As[k][m]
    __shared__ float Bs[BKk][BN];

    const int tid = threadIdx.x;
    const int row0 = blockIdx.y * BM;
    const int col0 = blockIdx.x * BN;

    const int tx = tid & 15;        // 0..15
    const int ty = tid >> 4;        // 0..15

    float acc[TM][TN];
    #pragma unroll
    for (int i = 0; i < TM; i++)
        #pragma unroll
        for (int j = 0; j < TN; j++) acc[i][j] = 0.f;

    // A loader: each thread loads one float4 of the 128x8 tile
    const int arow = tid >> 1;            // 0..127
    const int acol = (tid & 1) * 4;       // 0 or 4
    // B loader: each thread loads one float4 of the 8x128 tile
    const int brow = tid >> 5;            // 0..7
    const int bcol = (tid & 31) * 4;      // 0..124

    const float* Aptr = A + (size_t)(row0 + arow) * K + acol;
    const float* Bptr = B + (size_t)brow * N + col0 + bcol;

    for (int k0 = 0; k0 < K; k0 += BKk) {
        float4 a4 = *(const float4*)(Aptr + k0);
        As[acol + 0][arow] = a4.x;
        As[acol + 1][arow] = a4.y;
        As[acol + 2][arow] = a4.z;
        As[acol + 3][arow] = a4.w;
        *(float4*)&Bs[brow][bcol] = *(const float4*)(Bptr + (size_t)k0 * N);
        __syncthreads();

        #pragma unroll
        for (int k = 0; k < BKk; k++) {
            float af[TM], bf[TN];
            #pragma unroll
            for (int i = 0; i < TM; i += 4)
                *(float4*)&af[i] = *(const float4*)&As[k][ty * TM + i];
            #pragma unroll
            for (int j = 0; j < TN; j += 4)
                *(float4*)&bf[j] = *(const float4*)&Bs[k][tx * TN + j];
            #pragma unroll
            for (int i = 0; i < TM; i++)
                #pragma unroll
                for (int j = 0; j < TN; j++)
                    acc[i][j] = fmaf(af[i], bf[j], acc[i][j]);
        }
        __syncthreads();
    }

    #pragma unroll
    for (int i = 0; i < TM; i++) {
        const int r = row0 + ty * TM + i;
        #pragma unroll
        for (int j = 0; j < TN; j += 4) {
            const int c = col0 + tx * TN + j;
            float4 o;
            o.x = acc[i][j + 0] + bias[c + 0];
            o.y = acc[i][j + 1] + bias[c + 1];
            o.z = acc[i][j + 2] + bias[c + 2];
            o.w = acc[i][j + 3] + bias[c + 3];
            *(float4*)&C[(size_t)r * N + c] = o;
        }
    }
}

// ---------------------------------------------------------------------------
// Flash attention, fp32, causal. 1 thread = 1 query row.
// Block: 128 threads = 128 query rows. K/V tiles of 64 keys in shared.
// qkv layout: [b, s, 3, H, HD] row-major -> row stride 3072 floats.
// Output att: [b, s, H*HD] = [4096][1024].
// ---------------------------------------------------------------------------
#define QT 128
#define KT 64

__global__ __launch_bounds__(128)
void flash_attn(const float* __restrict__ qkv, const float* __restrict__ mask,
                float* __restrict__ att) {
    const int it = blockIdx.x;       // q tile index (0..15)
    const int h  = blockIdx.y;
    const int b  = blockIdx.z;
    const int r  = threadIdx.x;      // row within tile
    const int i  = it * QT + r;      // global query row

    __shared__ float4 Ks[KT][HD / 4];
    __shared__ float4 Vs[KT][HD / 4];
    __shared__ float  Lm[KT];

    // Load q row into registers (16 float4 = 64 floats)
    const float* qrow = qkv + ((size_t)(b * Ss + i) * 3) * Dd + h * HD;
    float4 q[16];
    #pragma unroll
    for (int c4 = 0; c4 < 16; c4++) q[c4] = ((const float4*)qrow)[c4];

    float acc[HD];
    #pragma unroll
    for (int d = 0; d < HD; d++) acc[d] = 0.f;
    float m = -1e30f, l = 0.f;
    const float scale = 0.125f;   // 1/sqrt(64)

    const int ntiles = 2 * it + 2;   // KT=64, QT=128

    for (int jt = 0; jt < ntiles; jt++) {
        const int j0 = jt * KT;
        // Cooperative K/V tile load: KT*16 = 1024 float4 per tile, 128 thr -> 8 each
        {
            const float* kbase = qkv + ((size_t)(b * Ss + j0) * 3 + 1) * Dd + h * HD;
            const float* vbase = qkv + ((size_t)(b * Ss + j0) * 3 + 2) * Dd + h * HD;
            #pragma unroll
            for (int t = 0; t < 8; t++) {
                int g   = t * 128 + r;        // 0..1023
                int row = g >> 4;
                int c4  = g & 15;
                Ks[row][c4] = *(const float4*)(kbase + (size_t)row * 3072 + c4 * 4);
                Vs[row][c4] = *(const float4*)(vbase + (size_t)row * 3072 + c4 * 4);
            }
            if (r < KT) Lm[r] = __logf(mask[b * Ss + j0 + r]);
        }
        __syncthreads();

        const int jmax = min(KT, i - j0 + 1);   // # of causally valid keys in tile

        for (int jc = 0; jc < KT; jc += 16) {
            if (jc >= jmax) break;   // no syncthreads inside this loop
            float s[16];
            #pragma unroll
            for (int jj = 0; jj < 16; jj++) {
                float a = 0.f;
                #pragma unroll
                for (int c4 = 0; c4 < 16; c4++) {
                    float4 kv = Ks[jc + jj][c4];   // broadcast LDS.128
                    a = fmaf(q[c4].x, kv.x, a);
                    a = fmaf(q[c4].y, kv.y, a);
                    a = fmaf(q[c4].z, kv.z, a);
                    a = fmaf(q[c4].w, kv.w, a);
                }
                s[jj] = a * scale + Lm[jc + jj];
            }
            if (jc + 16 > jmax) {
                #pragma unroll
                for (int jj = 0; jj < 16; jj++)
                    if (jc + jj >= jmax) s[jj] = -1e30f;
            }
            float mn = m;
            #pragma unroll
            for (int jj = 0; jj < 16; jj++) mn = fmaxf(mn, s[jj]);
            const float corr = __expf(m - mn);
            m = mn;
            l *= corr;
            #pragma unroll
            for (int d = 0; d < HD; d++) acc[d] *= corr;
            #pragma unroll
            for (int jj = 0; jj < 16; jj++) {
                const float p = __expf(s[jj] - m);
                l += p;
                #pragma unroll
                for (int c4 = 0; c4 < 16; c4++) {
                    float4 vv = Vs[jc + jj][c4];   // broadcast LDS.128
                    acc[c4 * 4 + 0] = fmaf(p, vv.x, acc[c4 * 4 + 0]);
                    acc[c4 * 4 + 1] = fmaf(p, vv.y, acc[c4 * 4 + 1]);
                    acc[c4 * 4 + 2] = fmaf(p, vv.z, acc[c4 * 4 + 2]);
                    acc[c4 * 4 + 3] = fmaf(p, vv.w, acc[c4 * 4 + 3]);
                }
            }
        }
        __syncthreads();
    }

    const float inv = 1.f / l;
    float* out = att + (size_t)(b * Ss + i) * Dd + h * HD;
    #pragma unroll
    for (int d = 0; d < HD; d += 4) {
        float4 o;
        o.x = acc[d + 0] * inv;
        o.y = acc[d + 1] * inv;
        o.z = acc[d + 2] * inv;
        o.w = acc[d + 3] * inv;
        *(float4*)(out + d) = o;
    }
}

// ---------------------------------------------------------------------------
// Launch
// ---------------------------------------------------------------------------
extern "C" void kernel_launch(void* const* d_in, const int* in_sizes, int n_in,
                              void* d_out, int out_size) {
    const float* x     = (const float*)d_in[0];
    const float* mask  = (const float*)d_in[1];
    const float* W_qkv = (const float*)d_in[2];
    const float* b_qkv = (const float*)d_in[3];
    const float* W_o   = (const float*)d_in[4];
    const float* b_o   = (const float*)d_in[5];
    float* out = (float*)d_out;

    float* qkv_ptr = nullptr;
    float* att_ptr = nullptr;
    cudaGetSymbolAddress((void**)&qkv_ptr, g_qkv);
    cudaGetSymbolAddress((void**)&att_ptr, g_att);

    // 1) QKV projection: [4096,1024] @ [1024,3072] + b_qkv
    sgemm_bias<<<dim3(3 * Dd / BN, Mrows / BM), 256>>>(
        x, W_qkv, b_qkv, qkv_ptr, Mrows, 3 * Dd, Dd);

    // 2) Flash attention (causal + key-side log(mask))
    flash_attn<<<dim3(Ss / QT, Hh, Bb), 128>>>(qkv_ptr, mask, att_ptr);

    // 3) Output projection: [4096,1024] @ [1024,1024] + b_o
    sgemm_bias<<<dim3(Dd / BN, Mrows / BM), 256>>>(
        att_ptr, W_o, b_o, out, Mrows, Dd, Dd);
}

// round 5
// speedup vs baseline: 1.9873x; 1.9873x over previous
#include <cuda_runtime.h>
#include <math.h>

#define Bb 2
#define Ss 2048
#define Dd 1024
#define Hh 16
#define HD 64
#define Mrows (Bb*Ss)          // 4096

__device__ float g_qkv[(size_t)Mrows * 3 * Dd];   // [4096][3072]
__device__ float g_att[(size_t)Mrows * Dd];       // [4096][1024]

// ===========================================================================
// Helpers
// ===========================================================================
__device__ __forceinline__ unsigned f2tf(float x) {
    unsigned u;
    asm("cvt.rna.tf32.f32 %0, %1;" : "=r"(u) : "f"(x));
    return u;
}

__device__ __forceinline__ void mma8(float* d, const unsigned* a,
                                     unsigned b0, unsigned b1) {
    asm volatile(
        "mma.sync.aligned.m16n8k8.row.col.f32.tf32.tf32.f32 "
        "{%0,%1,%2,%3}, {%4,%5,%6,%7}, {%8,%9}, {%0,%1,%2,%3};"
        : "+f"(d[0]), "+f"(d[1]), "+f"(d[2]), "+f"(d[3])
        : "r"(a[0]), "r"(a[1]), "r"(a[2]), "r"(a[3]), "r"(b0), "r"(b1));
}

// ===========================================================================
// tf32 mma.sync GEMM (3xTF32 split): C[M,N] = A[M,K] @ B[K,N] + bias
// Tile 128x128x16, 256 threads (8 warps, 2x4 -> 64x32 warp tiles),
// double-buffered SMEM, pitch-20 rows (conflict-free fragment LDS).
// SMEM words per buffer: Ahi[128*20], Alo, Bhi[128*20] (as [n][k]), Blo.
// ===========================================================================
#define GP 20
#define ASZ (128 * GP)          // 2560 words
#define BUFW (4 * ASZ)          // 10240 words per buffer
#define GEMM_SMEM_BYTES (2 * BUFW * 4)   // 81920 B

struct Pref {
    float4 a0, a1;   // A: two float4 (rows r, r+64)
    float4 b0, b1;   // B: row kk, cols tcol*4 and tcol*4+64
};

__device__ __forceinline__ void g_load(const float* __restrict__ A,
                                       const float* __restrict__ Bm,
                                       int K, int N, int row0, int col0, int k0,
                                       int tid, Pref& p) {
    const int r0 = tid >> 2;
    const int c4 = (tid & 3) * 4;
    p.a0 = *(const float4*)(A + (size_t)(row0 + r0) * K + k0 + c4);
    p.a1 = *(const float4*)(A + (size_t)(row0 + 64 + r0) * K + k0 + c4);
    const int kk = tid & 15;
    const int tcol = tid >> 4;
    const float* bp = Bm + (size_t)(k0 + kk) * N + col0 + tcol * 4;
    p.b0 = *(const float4*)bp;
    p.b1 = *(const float4*)(bp + 64);
}

__device__ __forceinline__ void s_store(unsigned* __restrict__ sm, int tid,
                                        const Pref& p) {
    const int r0 = tid >> 2;
    const int c4 = (tid & 3) * 4;
    #pragma unroll
    for (int half = 0; half < 2; half++) {
        float4 v = half ? p.a1 : p.a0;
        uint4 h, l;
        h.x = f2tf(v.x); l.x = f2tf(v.x - __uint_as_float(h.x));
        h.y = f2tf(v.y); l.y = f2tf(v.y - __uint_as_float(h.y));
        h.z = f2tf(v.z); l.z = f2tf(v.z - __uint_as_float(h.z));
        h.w = f2tf(v.w); l.w = f2tf(v.w - __uint_as_float(h.w));
        const int r = half * 64 + r0;
        *(uint4*)&sm[r * GP + c4] = h;
        *(uint4*)&sm[ASZ + r * GP + c4] = l;
    }
    const int kk = tid & 15;
    const int tcol = tid >> 4;
    #pragma unroll
    for (int half = 0; half < 2; half++) {
        float4 v = half ? p.b1 : p.b0;
        const float* vf = &v.x;
        #pragma unroll
        for (int j = 0; j < 4; j++) {
            const int n = tcol * 4 + j + half * 64;
            unsigned hb = f2tf(vf[j]);
            unsigned lb = f2tf(vf[j] - __uint_as_float(hb));
            sm[2 * ASZ + n * GP + kk] = hb;
            sm[3 * ASZ + n * GP + kk] = lb;
        }
    }
}

__global__ __launch_bounds__(256, 1)
void gemm_mma(const float* __restrict__ A, const float* __restrict__ Bm,
              const float* __restrict__ bias, float* __restrict__ C,
              int M, int N, int K) {
    extern __shared__ unsigned sm[];
    const int tid = threadIdx.x;
    const int lane = tid & 31, wid = tid >> 5;
    const int warpM = wid & 1, warpN = wid >> 1;
    const int gr = lane >> 2, tg = lane & 3;
    const int row0 = blockIdx.y * 128, col0 = blockIdx.x * 128;

    float acc[4][4][4];
    #pragma unroll
    for (int mi = 0; mi < 4; mi++)
        #pragma unroll
        for (int ni = 0; ni < 4; ni++)
            #pragma unroll
            for (int r = 0; r < 4; r++) acc[mi][ni][r] = 0.f;

    const int NT = K >> 4;
    Pref p;
    g_load(A, Bm, K, N, row0, col0, 0, tid, p);
    s_store(sm, tid, p);
    __syncthreads();

    for (int t = 0; t < NT; t++) {
        const int cur = t & 1;
        const bool more = (t + 1 < NT);
        if (more) g_load(A, Bm, K, N, row0, col0, (t + 1) << 4, tid, p);

        const unsigned* base = sm + cur * BUFW;
        #pragma unroll
        for (int ks = 0; ks < 2; ks++) {
            const int acol = ks * 8 + tg;
            unsigned ah[4][4], al[4][4];
            #pragma unroll
            for (int mi = 0; mi < 4; mi++) {
                const int rb = warpM * 64 + mi * 16 + gr;
                ah[mi][0] = base[rb * GP + acol];
                ah[mi][1] = base[(rb + 8) * GP + acol];
                ah[mi][2] = base[rb * GP + acol + 4];
                ah[mi][3] = base[(rb + 8) * GP + acol + 4];
                al[mi][0] = base[ASZ + rb * GP + acol];
                al[mi][1] = base[ASZ + (rb + 8) * GP + acol];
                al[mi][2] = base[ASZ + rb * GP + acol + 4];
                al[mi][3] = base[ASZ + (rb + 8) * GP + acol + 4];
            }
            unsigned bh[4][2], bl[4][2];
            #pragma unroll
            for (int ni = 0; ni < 4; ni++) {
                const int nb = warpN * 32 + ni * 8 + gr;
                bh[ni][0] = base[2 * ASZ + nb * GP + ks * 8 + tg];
                bh[ni][1] = base[2 * ASZ + nb * GP + ks * 8 + tg + 4];
                bl[ni][0] = base[3 * ASZ + nb * GP + ks * 8 + tg];
                bl[ni][1] = base[3 * ASZ + nb * GP + ks * 8 + tg + 4];
            }
            #pragma unroll
            for (int mi = 0; mi < 4; mi++)
                #pragma unroll
                for (int ni = 0; ni < 4; ni++) {
                    mma8(acc[mi][ni], ah[mi], bh[ni][0], bh[ni][1]);
                    mma8(acc[mi][ni], ah[mi], bl[ni][0], bl[ni][1]);
                    mma8(acc[mi][ni], al[mi], bh[ni][0], bh[ni][1]);
                }
        }

        if (more) s_store(sm + ((t + 1) & 1) * BUFW, tid, p);
        __syncthreads();
    }

    // Epilogue: register frags -> global, + bias
    #pragma unroll
    for (int mi = 0; mi < 4; mi++) {
        const int r = row0 + warpM * 64 + mi * 16 + gr;
        #pragma unroll
        for (int ni = 0; ni < 4; ni++) {
            const int c = col0 + warpN * 32 + ni * 8 + tg * 2;
            const float bx = bias[c], by = bias[c + 1];
            float2 o0, o1;
            o0.x = acc[mi][ni][0] + bx;
            o0.y = acc[mi][ni][1] + by;
            o1.x = acc[mi][ni][2] + bx;
            o1.y = acc[mi][ni][3] + by;
            *(float2*)&C[(size_t)r * N + c] = o0;
            *(float2*)&C[(size_t)(r + 8) * N + c] = o1;
        }
    }
}

// ===========================================================================
// Flash attention, fp32, causal. 2 lanes per query row (lane l pairs l^16).
// 256 threads = 8 warps x 16 rows = 128 rows/block. K/V tiles of 64 in SMEM.
// ===========================================================================
#define QT 128
#define KT 64

__global__ __launch_bounds__(256)
void flash_attn2(const float* __restrict__ qkv, const float* __restrict__ mask,
                 float* __restrict__ att) {
    const int it = (gridDim.x - 1) - blockIdx.x;   // heavy tiles first
    const int h  = blockIdx.y;
    const int b  = blockIdx.z;
    const int tid  = threadIdx.x;
    const int wid  = tid >> 5;
    const int lane = tid & 31;
    const int row  = wid * 16 + (lane & 15);
    const int half = lane >> 4;
    const int i    = it * QT + row;

    __shared__ float4 Ks[KT][16];
    __shared__ float4 Vs[KT][16];
    __shared__ float  Lm[KT];

    const float* qrow = qkv + ((size_t)(b * Ss + i) * 3) * Dd + h * HD + half * 32;
    float4 q[8];
    #pragma unroll
    for (int c4 = 0; c4 < 8; c4++) q[c4] = ((const float4*)qrow)[c4];

    float acc[32];
    #pragma unroll
    for (int d = 0; d < 32; d++) acc[d] = 0.f;
    float m = -1e30f, l = 0.f;

    const int ntiles = 2 * it + 2;
    const int row_hi = it * QT + wid * 16 + 15;   // last row of this warp's band

    for (int jt = 0; jt < ntiles; jt++) {
        const int j0 = jt * KT;
        {
            const float* kbase = qkv + ((size_t)(b * Ss + j0) * 3 + 1) * Dd + h * HD;
            const float* vbase = qkv + ((size_t)(b * Ss + j0) * 3 + 2) * Dd + h * HD;
            #pragma unroll
            for (int p = 0; p < 4; p++) {
                int g   = p * 256 + tid;
                int r   = g >> 4;
                int c4  = g & 15;
                Ks[r][c4] = *(const float4*)(kbase + (size_t)r * 3072 + c4 * 4);
                Vs[r][c4] = *(const float4*)(vbase + (size_t)r * 3072 + c4 * 4);
            }
            if (tid < KT) Lm[tid] = __logf(mask[b * Ss + j0 + tid]);
        }
        __syncthreads();

        const int jmaxw = min(KT, row_hi - j0 + 1);  // warp-uniform bound
        const int jmaxl = i - j0 + 1;                // per-lane causal bound

        for (int jc = 0; jc < KT; jc += 16) {
            if (jc >= jmaxw) break;                  // warp-uniform break
            float s[16];
            #pragma unroll
            for (int jj = 0; jj < 16; jj++) {
                float a = 0.f;
                const float4* kp = &Ks[jc + jj][half * 8];
                #pragma unroll
                for (int c4 = 0; c4 < 8; c4++) {
                    float4 kv = kp[c4];
                    a = fmaf(q[c4].x, kv.x, a);
                    a = fmaf(q[c4].y, kv.y, a);
                    a = fmaf(q[c4].z, kv.z, a);
                    a = fmaf(q[c4].w, kv.w, a);
                }
                a += __shfl_xor_sync(0xffffffffu, a, 16);
                s[jj] = a * 0.125f + Lm[jc + jj];
            }
            if (jc + 16 > jmaxl) {
                #pragma unroll
                for (int jj = 0; jj < 16; jj++)
                    if (jc + jj >= jmaxl) s[jj] = -1e30f;
            }
            float mn = m;
            #pragma unroll
            for (int jj = 0; jj < 16; jj++) mn = fmaxf(mn, s[jj]);
            const float corr = __expf(m - mn);
            m = mn;
            l *= corr;
            #pragma unroll
            for (int d = 0; d < 32; d++) acc[d] *= corr;
            #pragma unroll
            for (int jj = 0; jj < 16; jj++) {
                const float p = __expf(s[jj] - m);
                l += p;
                const float4* vp = &Vs[jc + jj][half * 8];
                #pragma unroll
                for (int c4 = 0; c4 < 8; c4++) {
                    float4 vv = vp[c4];
                    acc[c4 * 4 + 0] = fmaf(p, vv.x, acc[c4 * 4 + 0]);
                    acc[c4 * 4 + 1] = fmaf(p, vv.y, acc[c4 * 4 + 1]);
                    acc[c4 * 4 + 2] = fmaf(p, vv.z, acc[c4 * 4 + 2]);
                    acc[c4 * 4 + 3] = fmaf(p, vv.w, acc[c4 * 4 + 3]);
                }
            }
        }
        __syncthreads();
    }

    const float inv = 1.f / l;
    float* out = att + (size_t)(b * Ss + i) * Dd + h * HD + half * 32;
    #pragma unroll
    for (int d = 0; d < 32; d += 4) {
        float4 o;
        o.x = acc[d + 0] * inv;
        o.y = acc[d + 1] * inv;
        o.z = acc[d + 2] * inv;
        o.w = acc[d + 3] * inv;
        *(float4*)(out + d) = o;
    }
}

// ===========================================================================
// Launch
// ===========================================================================
extern "C" void kernel_launch(void* const* d_in, const int* in_sizes, int n_in,
                              void* d_out, int out_size) {
    const float* x     = (const float*)d_in[0];
    const float* mask  = (const float*)d_in[1];
    const float* W_qkv = (const float*)d_in[2];
    const float* b_qkv = (const float*)d_in[3];
    const float* W_o   = (const float*)d_in[4];
    const float* b_o   = (const float*)d_in[5];
    float* out = (float*)d_out;

    float* qkv_ptr = nullptr;
    float* att_ptr = nullptr;
    cudaGetSymbolAddress((void**)&qkv_ptr, g_qkv);
    cudaGetSymbolAddress((void**)&att_ptr, g_att);

    cudaFuncSetAttribute(gemm_mma, cudaFuncAttributeMaxDynamicSharedMemorySize,
                         GEMM_SMEM_BYTES);

    // 1) QKV projection: [4096,1024] @ [1024,3072] + b_qkv
    gemm_mma<<<dim3(3 * Dd / 128, Mrows / 128), 256, GEMM_SMEM_BYTES>>>(
        x, W_qkv, b_qkv, qkv_ptr, Mrows, 3 * Dd, Dd);

    // 2) Flash attention (causal + key-side log(mask))
    flash_attn2<<<dim3(Ss / QT, Hh, Bb), 256>>>(qkv_ptr, mask, att_ptr);

    // 3) Output projection: [4096,1024] @ [1024,1024] + b_o
    gemm_mma<<<dim3(Dd / 128, Mrows / 128), 256, GEMM_SMEM_BYTES>>>(
        att_ptr, W_o, b_o, out, Mrows, Dd, Dd);
}

// round 8
// speedup vs baseline: 3.0565x; 1.5380x over previous
#include <cuda_runtime.h>
#include <math.h>

#define Bb 2
#define Ss 2048
#define Dd 1024
#define Hh 16
#define HD 64
#define Mrows (Bb*Ss)          // 4096

__device__ float g_qkv[(size_t)Mrows * 3 * Dd];   // [4096][3072]
__device__ float g_att[(size_t)Mrows * Dd];       // [4096][1024]

// ===========================================================================
// Helpers
// ===========================================================================
__device__ __forceinline__ unsigned f2tf(float x) {
    unsigned u;
    asm("cvt.rna.tf32.f32 %0, %1;" : "=r"(u) : "f"(x));
    return u;
}

__device__ __forceinline__ void mma8(float* d, const unsigned* a,
                                     unsigned b0, unsigned b1) {
    asm volatile(
        "mma.sync.aligned.m16n8k8.row.col.f32.tf32.tf32.f32 "
        "{%0,%1,%2,%3}, {%4,%5,%6,%7}, {%8,%9}, {%0,%1,%2,%3};"
        : "+f"(d[0]), "+f"(d[1]), "+f"(d[2]), "+f"(d[3])
        : "r"(a[0]), "r"(a[1]), "r"(a[2]), "r"(a[3]), "r"(b0), "r"(b1));
}

// ===========================================================================
// tf32 mma.sync GEMM (3xTF32 split): C[M,N] = A[M,K] @ B[K,N] + bias
// (unchanged — passing, tensor 43.6%)
// ===========================================================================
#define GP 20
#define ASZ (128 * GP)
#define BUFW (4 * ASZ)
#define GEMM_SMEM_BYTES (2 * BUFW * 4)   // 81920 B

struct Pref {
    float4 a0, a1;
    float4 b0, b1;
};

__device__ __forceinline__ void g_load(const float* __restrict__ A,
                                       const float* __restrict__ Bm,
                                       int K, int N, int row0, int col0, int k0,
                                       int tid, Pref& p) {
    const int r0 = tid >> 2;
    const int c4 = (tid & 3) * 4;
    p.a0 = *(const float4*)(A + (size_t)(row0 + r0) * K + k0 + c4);
    p.a1 = *(const float4*)(A + (size_t)(row0 + 64 + r0) * K + k0 + c4);
    const int kk = tid & 15;
    const int tcol = tid >> 4;
    const float* bp = Bm + (size_t)(k0 + kk) * N + col0 + tcol * 4;
    p.b0 = *(const float4*)bp;
    p.b1 = *(const float4*)(bp + 64);
}

__device__ __forceinline__ void s_store(unsigned* __restrict__ sm, int tid,
                                        const Pref& p) {
    const int r0 = tid >> 2;
    const int c4 = (tid & 3) * 4;
    #pragma unroll
    for (int half = 0; half < 2; half++) {
        float4 v = half ? p.a1 : p.a0;
        uint4 h, l;
        h.x = f2tf(v.x); l.x = f2tf(v.x - __uint_as_float(h.x));
        h.y = f2tf(v.y); l.y = f2tf(v.y - __uint_as_float(h.y));
        h.z = f2tf(v.z); l.z = f2tf(v.z - __uint_as_float(h.z));
        h.w = f2tf(v.w); l.w = f2tf(v.w - __uint_as_float(h.w));
        const int r = half * 64 + r0;
        *(uint4*)&sm[r * GP + c4] = h;
        *(uint4*)&sm[ASZ + r * GP + c4] = l;
    }
    const int kk = tid & 15;
    const int tcol = tid >> 4;
    #pragma unroll
    for (int half = 0; half < 2; half++) {
        float4 v = half ? p.b1 : p.b0;
        const float* vf = &v.x;
        #pragma unroll
        for (int j = 0; j < 4; j++) {
            const int n = tcol * 4 + j + half * 64;
            unsigned hb = f2tf(vf[j]);
            unsigned lb = f2tf(vf[j] - __uint_as_float(hb));
            sm[2 * ASZ + n * GP + kk] = hb;
            sm[3 * ASZ + n * GP + kk] = lb;
        }
    }
}

__global__ __launch_bounds__(256, 1)
void gemm_mma(const float* __restrict__ A, const float* __restrict__ Bm,
              const float* __restrict__ bias, float* __restrict__ C,
              int M, int N, int K) {
    extern __shared__ unsigned sm[];
    const int tid = threadIdx.x;
    const int lane = tid & 31, wid = tid >> 5;
    const int warpM = wid & 1, warpN = wid >> 1;
    const int gr = lane >> 2, tg = lane & 3;
    const int row0 = blockIdx.y * 128, col0 = blockIdx.x * 128;

    float acc[4][4][4];
    #pragma unroll
    for (int mi = 0; mi < 4; mi++)
        #pragma unroll
        for (int ni = 0; ni < 4; ni++)
            #pragma unroll
            for (int r = 0; r < 4; r++) acc[mi][ni][r] = 0.f;

    const int NT = K >> 4;
    Pref p;
    g_load(A, Bm, K, N, row0, col0, 0, tid, p);
    s_store(sm, tid, p);
    __syncthreads();

    for (int t = 0; t < NT; t++) {
        const int cur = t & 1;
        const bool more = (t + 1 < NT);
        if (more) g_load(A, Bm, K, N, row0, col0, (t + 1) << 4, tid, p);

        const unsigned* base = sm + cur * BUFW;
        #pragma unroll
        for (int ks = 0; ks < 2; ks++) {
            const int acol = ks * 8 + tg;
            unsigned ah[4][4], al[4][4];
            #pragma unroll
            for (int mi = 0; mi < 4; mi++) {
                const int rb = warpM * 64 + mi * 16 + gr;
                ah[mi][0] = base[rb * GP + acol];
                ah[mi][1] = base[(rb + 8) * GP + acol];
                ah[mi][2] = base[rb * GP + acol + 4];
                ah[mi][3] = base[(rb + 8) * GP + acol + 4];
                al[mi][0] = base[ASZ + rb * GP + acol];
                al[mi][1] = base[ASZ + (rb + 8) * GP + acol];
                al[mi][2] = base[ASZ + rb * GP + acol + 4];
                al[mi][3] = base[ASZ + (rb + 8) * GP + acol + 4];
            }
            unsigned bh[4][2], bl[4][2];
            #pragma unroll
            for (int ni = 0; ni < 4; ni++) {
                const int nb = warpN * 32 + ni * 8 + gr;
                bh[ni][0] = base[2 * ASZ + nb * GP + ks * 8 + tg];
                bh[ni][1] = base[2 * ASZ + nb * GP + ks * 8 + tg + 4];
                bl[ni][0] = base[3 * ASZ + nb * GP + ks * 8 + tg];
                bl[ni][1] = base[3 * ASZ + nb * GP + ks * 8 + tg + 4];
            }
            #pragma unroll
            for (int mi = 0; mi < 4; mi++)
                #pragma unroll
                for (int ni = 0; ni < 4; ni++) {
                    mma8(acc[mi][ni], ah[mi], bh[ni][0], bh[ni][1]);
                    mma8(acc[mi][ni], ah[mi], bl[ni][0], bl[ni][1]);
                    mma8(acc[mi][ni], al[mi], bh[ni][0], bh[ni][1]);
                }
        }

        if (more) s_store(sm + ((t + 1) & 1) * BUFW, tid, p);
        __syncthreads();
    }

    #pragma unroll
    for (int mi = 0; mi < 4; mi++) {
        const int r = row0 + warpM * 64 + mi * 16 + gr;
        #pragma unroll
        for (int ni = 0; ni < 4; ni++) {
            const int c = col0 + warpN * 32 + ni * 8 + tg * 2;
            const float bx = bias[c], by = bias[c + 1];
            float2 o0, o1;
            o0.x = acc[mi][ni][0] + bx;
            o0.y = acc[mi][ni][1] + by;
            o1.x = acc[mi][ni][2] + bx;
            o1.y = acc[mi][ni][3] + by;
            *(float2*)&C[(size_t)r * N + c] = o0;
            *(float2*)&C[(size_t)(r + 8) * N + c] = o1;
        }
    }
}

// ===========================================================================
// Flash attention with mma.sync tf32. 128 q-rows/block, 8 warps x 16 rows.
// KV tiles of 64. Q frags register-resident; P via warp-private SMEM.
// FIX vs R6: V transpose load now covers ALL 64 j rows (was only j<32).
// ===========================================================================
#define AP 68
#define KT 64
#define ATT_SMEM_FLOATS (128 * AP + 8 * 16 * AP + 64)
#define ATT_SMEM_BYTES (ATT_SMEM_FLOATS * 4)

__global__ __launch_bounds__(256, 1)
void flash_mma(const float* __restrict__ qkv, const float* __restrict__ mask,
               float* __restrict__ att) {
    extern __shared__ float smf[];
    float* Ks = smf;                        // [j][d] pitch AP (64 rows)
    float* Vs = smf + 64 * AP;              // [d][j] pitch AP (64 rows)
    float* Pm = smf + 128 * AP;             // per-warp [16][AP]
    float* Lm = smf + 128 * AP + 8 * 16 * AP;

    const int it = (gridDim.x - 1) - blockIdx.x;   // heavy tiles first
    const int h  = blockIdx.y;
    const int b  = blockIdx.z;
    const int tid  = threadIdx.x;
    const int wid  = tid >> 5;
    const int lane = tid & 31;
    const int gr = lane >> 2, tg = lane & 3;
    const int i0 = it * 128 + wid * 16 + gr;       // thread's first q row
    float* Pw = Pm + wid * (16 * AP);

    // ---- Stage Q tile [128][64] into smf (pitch AP), then frags to regs ----
    {
        const float* qb = qkv + ((size_t)(b * Ss + it * 128) * 3) * Dd + h * HD;
        #pragma unroll
        for (int p = 0; p < 8; p++) {
            int g = p * 256 + tid;
            int r = g >> 4, c4 = g & 15;
            float4 v = *(const float4*)(qb + (size_t)r * 3072 + c4 * 4);
            *(float4*)&smf[r * AP + c4 * 4] = v;
        }
    }
    __syncthreads();
    unsigned qf[8][4];
    {
        const int rb = wid * 16 + gr;
        #pragma unroll
        for (int kb = 0; kb < 8; kb++) {
            qf[kb][0] = f2tf(smf[rb * AP + kb * 8 + tg]);
            qf[kb][1] = f2tf(smf[(rb + 8) * AP + kb * 8 + tg]);
            qf[kb][2] = f2tf(smf[rb * AP + kb * 8 + tg + 4]);
            qf[kb][3] = f2tf(smf[(rb + 8) * AP + kb * 8 + tg + 4]);
        }
    }

    float oacc[8][4];
    #pragma unroll
    for (int nb = 0; nb < 8; nb++)
        #pragma unroll
        for (int r = 0; r < 4; r++) oacc[nb][r] = 0.f;
    float m0 = -1e30f, m1 = -1e30f, l0 = 0.f, l1 = 0.f;

    const int ntiles = 2 * it + 2;

    for (int jt = 0; jt < ntiles; jt++) {
        const int j0 = jt * KT;
        __syncthreads();   // previous tile fully consumed
        // ---- K tile [j][d], tf32-rounded ----
        {
            const float* kb_ = qkv + ((size_t)(b * Ss + j0) * 3 + 1) * Dd + h * HD;
            #pragma unroll
            for (int p = 0; p < 4; p++) {
                int g = p * 256 + tid;
                int r = g >> 4, c4 = g & 15;
                float4 v = *(const float4*)(kb_ + (size_t)r * 3072 + c4 * 4);
                uint4 u;
                u.x = f2tf(v.x); u.y = f2tf(v.y);
                u.z = f2tf(v.z); u.w = f2tf(v.w);
                *(uint4*)&Ks[r * AP + c4 * 4] = u;
            }
        }
        // ---- V tile transposed: warp w owns d in [8w, 8w+8), ALL 64 j ----
        {
            const float* vb = qkv + ((size_t)(b * Ss + j0) * 3 + 2) * Dd + h * HD
                              + wid * 8;
            #pragma unroll
            for (int jh = 0; jh < 2; jh++) {
                const int j = jh * 32 + lane;
                float4 v0 = *(const float4*)(vb + (size_t)j * 3072);
                float4 v1 = *(const float4*)(vb + (size_t)j * 3072 + 4);
                const float* vf0 = &v0.x;
                const float* vf1 = &v1.x;
                #pragma unroll
                for (int ii = 0; ii < 4; ii++) {
                    Vs[(wid * 8 + ii) * AP + j] =
                        __uint_as_float(f2tf(vf0[ii]));
                    Vs[(wid * 8 + 4 + ii) * AP + j] =
                        __uint_as_float(f2tf(vf1[ii]));
                }
            }
        }
        if (tid < KT) Lm[tid] = __logf(mask[b * Ss + j0 + tid]);
        __syncthreads();

        // ---- S = Q K^T (64 MMAs) ----
        float sacc[8][4];
        #pragma unroll
        for (int nb = 0; nb < 8; nb++) {
            sacc[nb][0] = sacc[nb][1] = sacc[nb][2] = sacc[nb][3] = 0.f;
            #pragma unroll
            for (int kb = 0; kb < 8; kb++) {
                unsigned b0 = __float_as_uint(Ks[(nb * 8 + gr) * AP + kb * 8 + tg]);
                unsigned b1 = __float_as_uint(Ks[(nb * 8 + gr) * AP + kb * 8 + tg + 4]);
                mma8(sacc[nb], qf[kb], b0, b1);
            }
        }

        // ---- scale + logmask + causal ----
        const bool partial = (j0 + KT - 1 > i0);   // needs per-element mask
        #pragma unroll
        for (int nb = 0; nb < 8; nb++) {
            const int c = nb * 8 + 2 * tg;
            const float lmx = Lm[c], lmy = Lm[c + 1];
            sacc[nb][0] = sacc[nb][0] * 0.125f + lmx;
            sacc[nb][1] = sacc[nb][1] * 0.125f + lmy;
            sacc[nb][2] = sacc[nb][2] * 0.125f + lmx;
            sacc[nb][3] = sacc[nb][3] * 0.125f + lmy;
            if (partial) {
                const int jcx = j0 + c, jcy = j0 + c + 1;
                if (jcx > i0)     sacc[nb][0] = -1e30f;
                if (jcy > i0)     sacc[nb][1] = -1e30f;
                if (jcx > i0 + 8) sacc[nb][2] = -1e30f;
                if (jcy > i0 + 8) sacc[nb][3] = -1e30f;
            }
        }

        // ---- online softmax (rows i0, i0+8) ----
        float mx0 = -1e30f, mx1 = -1e30f;
        #pragma unroll
        for (int nb = 0; nb < 8; nb++) {
            mx0 = fmaxf(mx0, fmaxf(sacc[nb][0], sacc[nb][1]));
            mx1 = fmaxf(mx1, fmaxf(sacc[nb][2], sacc[nb][3]));
        }
        mx0 = fmaxf(mx0, __shfl_xor_sync(0xffffffffu, mx0, 1));
        mx0 = fmaxf(mx0, __shfl_xor_sync(0xffffffffu, mx0, 2));
        mx1 = fmaxf(mx1, __shfl_xor_sync(0xffffffffu, mx1, 1));
        mx1 = fmaxf(mx1, __shfl_xor_sync(0xffffffffu, mx1, 2));
        const float nm0 = fmaxf(m0, mx0), nm1 = fmaxf(m1, mx1);
        const float c0 = __expf(m0 - nm0), c1 = __expf(m1 - nm1);
        m0 = nm0; m1 = nm1;

        float ls0 = 0.f, ls1 = 0.f;
        #pragma unroll
        for (int nb = 0; nb < 8; nb++) {
            const float p0 = __expf(sacc[nb][0] - m0);
            const float p1 = __expf(sacc[nb][1] - m0);
            const float p2 = __expf(sacc[nb][2] - m1);
            const float p3 = __expf(sacc[nb][3] - m1);
            ls0 += p0 + p1;
            ls1 += p2 + p3;
            const int c = nb * 8 + 2 * tg;
            float2 w0, w1;
            w0.x = __uint_as_float(f2tf(p0));
            w0.y = __uint_as_float(f2tf(p1));
            w1.x = __uint_as_float(f2tf(p2));
            w1.y = __uint_as_float(f2tf(p3));
            *(float2*)&Pw[gr * AP + c] = w0;
            *(float2*)&Pw[(gr + 8) * AP + c] = w1;
        }
        ls0 += __shfl_xor_sync(0xffffffffu, ls0, 1);
        ls0 += __shfl_xor_sync(0xffffffffu, ls0, 2);
        ls1 += __shfl_xor_sync(0xffffffffu, ls1, 1);
        ls1 += __shfl_xor_sync(0xffffffffu, ls1, 2);
        l0 = l0 * c0 + ls0;
        l1 = l1 * c1 + ls1;
        #pragma unroll
        for (int nb = 0; nb < 8; nb++) {
            oacc[nb][0] *= c0; oacc[nb][1] *= c0;
            oacc[nb][2] *= c1; oacc[nb][3] *= c1;
        }
        __syncwarp();

        // ---- O += P V (64 MMAs) ----
        #pragma unroll
        for (int kb = 0; kb < 8; kb++) {
            unsigned af[4];
            af[0] = __float_as_uint(Pw[gr * AP + kb * 8 + tg]);
            af[1] = __float_as_uint(Pw[(gr + 8) * AP + kb * 8 + tg]);
            af[2] = __float_as_uint(Pw[gr * AP + kb * 8 + tg + 4]);
            af[3] = __float_as_uint(Pw[(gr + 8) * AP + kb * 8 + tg + 4]);
            #pragma unroll
            for (int nb = 0; nb < 8; nb++) {
                unsigned b0 = __float_as_uint(Vs[(nb * 8 + gr) * AP + kb * 8 + tg]);
                unsigned b1 = __float_as_uint(Vs[(nb * 8 + gr) * AP + kb * 8 + tg + 4]);
                mma8(oacc[nb], af, b0, b1);
            }
        }
    }

    // ---- epilogue ----
    const float inv0 = 1.f / l0, inv1 = 1.f / l1;
    float* out0 = att + (size_t)(b * Ss + i0) * Dd + h * HD;
    float* out1 = out0 + (size_t)8 * Dd;
    #pragma unroll
    for (int nb = 0; nb < 8; nb++) {
        const int c = nb * 8 + 2 * tg;
        float2 o0, o1;
        o0.x = oacc[nb][0] * inv0;
        o0.y = oacc[nb][1] * inv0;
        o1.x = oacc[nb][2] * inv1;
        o1.y = oacc[nb][3] * inv1;
        *(float2*)&out0[c] = o0;
        *(float2*)&out1[c] = o1;
    }
}

// ===========================================================================
// Launch
// ===========================================================================
extern "C" void kernel_launch(void* const* d_in, const int* in_sizes, int n_in,
                              void* d_out, int out_size) {
    const float* x     = (const float*)d_in[0];
    const float* mask  = (const float*)d_in[1];
    const float* W_qkv = (const float*)d_in[2];
    const float* b_qkv = (const float*)d_in[3];
    const float* W_o   = (const float*)d_in[4];
    const float* b_o   = (const float*)d_in[5];
    float* out = (float*)d_out;

    float* qkv_ptr = nullptr;
    float* att_ptr = nullptr;
    cudaGetSymbolAddress((void**)&qkv_ptr, g_qkv);
    cudaGetSymbolAddress((void**)&att_ptr, g_att);

    cudaFuncSetAttribute(gemm_mma, cudaFuncAttributeMaxDynamicSharedMemorySize,
                         GEMM_SMEM_BYTES);
    cudaFuncSetAttribute(flash_mma, cudaFuncAttributeMaxDynamicSharedMemorySize,
                         ATT_SMEM_BYTES);

    // 1) QKV projection
    gemm_mma<<<dim3(3 * Dd / 128, Mrows / 128), 256, GEMM_SMEM_BYTES>>>(
        x, W_qkv, b_qkv, qkv_ptr, Mrows, 3 * Dd, Dd);

    // 2) Flash attention (tensorized)
    flash_mma<<<dim3(Ss / 128, Hh, Bb), 256, ATT_SMEM_BYTES>>>(
        qkv_ptr, mask, att_ptr);

    // 3) Output projection
    gemm_mma<<<dim3(Dd / 128, Mrows / 128), 256, GEMM_SMEM_BYTES>>>(
        att_ptr, W_o, b_o, out, Mrows, Dd, Dd);
}

// round 9
// speedup vs baseline: 3.9510x; 1.2926x over previous
#include <cuda_runtime.h>
#include <math.h>

#define Bb 2
#define Ss 2048
#define Dd 1024
#define Hh 16
#define HD 64
#define Mrows (Bb*Ss)          // 4096

__device__ float g_qkv[(size_t)Mrows * 3 * Dd];   // [4096][3072]
__device__ float g_att[(size_t)Mrows * Dd];       // [4096][1024]

// ===========================================================================
// Helpers
// ===========================================================================
__device__ __forceinline__ unsigned f2tf(float x) {
    unsigned u;
    asm("cvt.rna.tf32.f32 %0, %1;" : "=r"(u) : "f"(x));
    return u;
}

__device__ __forceinline__ void mma8(float* d, const unsigned* a,
                                     unsigned b0, unsigned b1) {
    asm volatile(
        "mma.sync.aligned.m16n8k8.row.col.f32.tf32.tf32.f32 "
        "{%0,%1,%2,%3}, {%4,%5,%6,%7}, {%8,%9}, {%0,%1,%2,%3};"
        : "+f"(d[0]), "+f"(d[1]), "+f"(d[2]), "+f"(d[3])
        : "r"(a[0]), "r"(a[1]), "r"(a[2]), "r"(a[3]), "r"(b0), "r"(b1));
}

// ===========================================================================
// tf32 mma.sync GEMM, 2-term split (A=hi+lo exact, B rounded once):
//   C = (Ah+Al) @ tf32(B) + bias   -> rel err ~1.4e-4 rms
// Tile 128x128x16, 512 threads (16 warps, 4x4 -> 32x32 warp tiles),
// double-buffered SMEM pitch-20 (conflict-free fragment LDS).
// Per buffer: Ahi[128*20], Alo[128*20], Bh[128*20] ([n][k]).
// ===========================================================================
#define GP 20
#define ASZ (128 * GP)          // 2560 words
#define BUFW (3 * ASZ)          // 7680 words per buffer
#define GEMM_SMEM_BYTES (2 * BUFW * 4)   // 61440 B

struct Pref {
    float4 a;                  // A: one float4 (row r, 4 k's)
    float b0, b1, b2, b3;      // B: col n, k = kq..kq+3
};

__device__ __forceinline__ void g_load(const float* __restrict__ A,
                                       const float* __restrict__ Bm,
                                       int K, int N, int row0, int col0, int k0,
                                       int tid, Pref& p) {
    const int r = tid >> 2;
    const int c4 = (tid & 3) * 4;
    p.a = *(const float4*)(A + (size_t)(row0 + r) * K + k0 + c4);
    const int n = tid & 127;
    const int kq = (tid >> 7) * 4;
    const float* bp = Bm + (size_t)(k0 + kq) * N + col0 + n;
    p.b0 = bp[0];
    p.b1 = bp[(size_t)N];
    p.b2 = bp[(size_t)2 * N];
    p.b3 = bp[(size_t)3 * N];
}

__device__ __forceinline__ void s_store(unsigned* __restrict__ sm, int tid,
                                        const Pref& p) {
    const int r = tid >> 2;
    const int c4 = (tid & 3) * 4;
    uint4 h, l;
    h.x = f2tf(p.a.x); l.x = f2tf(p.a.x - __uint_as_float(h.x));
    h.y = f2tf(p.a.y); l.y = f2tf(p.a.y - __uint_as_float(h.y));
    h.z = f2tf(p.a.z); l.z = f2tf(p.a.z - __uint_as_float(h.z));
    h.w = f2tf(p.a.w); l.w = f2tf(p.a.w - __uint_as_float(h.w));
    *(uint4*)&sm[r * GP + c4] = h;
    *(uint4*)&sm[ASZ + r * GP + c4] = l;

    const int n = tid & 127;
    const int kq = (tid >> 7) * 4;
    uint4 bq;
    bq.x = f2tf(p.b0);
    bq.y = f2tf(p.b1);
    bq.z = f2tf(p.b2);
    bq.w = f2tf(p.b3);
    *(uint4*)&sm[2 * ASZ + n * GP + kq] = bq;
}

__global__ __launch_bounds__(512, 1)
void gemm_mma(const float* __restrict__ A, const float* __restrict__ Bm,
              const float* __restrict__ bias, float* __restrict__ C,
              int M, int N, int K) {
    extern __shared__ unsigned sm[];
    const int tid = threadIdx.x;
    const int lane = tid & 31, wid = tid >> 5;
    const int warpM = wid & 3, warpN = wid >> 2;
    const int gr = lane >> 2, tg = lane & 3;
    const int row0 = blockIdx.y * 128, col0 = blockIdx.x * 128;

    float acc[2][4][4];
    #pragma unroll
    for (int mi = 0; mi < 2; mi++)
        #pragma unroll
        for (int ni = 0; ni < 4; ni++)
            #pragma unroll
            for (int r = 0; r < 4; r++) acc[mi][ni][r] = 0.f;

    const int NT = K >> 4;
    Pref p;
    g_load(A, Bm, K, N, row0, col0, 0, tid, p);
    s_store(sm, tid, p);
    __syncthreads();

    for (int t = 0; t < NT; t++) {
        const int cur = t & 1;
        const bool more = (t + 1 < NT);
        if (more) g_load(A, Bm, K, N, row0, col0, (t + 1) << 4, tid, p);

        const unsigned* base = sm + cur * BUFW;
        #pragma unroll
        for (int ks = 0; ks < 2; ks++) {
            const int acol = ks * 8 + tg;
            unsigned ah[2][4], al[2][4];
            #pragma unroll
            for (int mi = 0; mi < 2; mi++) {
                const int rb = warpM * 32 + mi * 16 + gr;
                ah[mi][0] = base[rb * GP + acol];
                ah[mi][1] = base[(rb + 8) * GP + acol];
                ah[mi][2] = base[rb * GP + acol + 4];
                ah[mi][3] = base[(rb + 8) * GP + acol + 4];
                al[mi][0] = base[ASZ + rb * GP + acol];
                al[mi][1] = base[ASZ + (rb + 8) * GP + acol];
                al[mi][2] = base[ASZ + rb * GP + acol + 4];
                al[mi][3] = base[ASZ + (rb + 8) * GP + acol + 4];
            }
            unsigned bh[4][2];
            #pragma unroll
            for (int ni = 0; ni < 4; ni++) {
                const int nb = warpN * 32 + ni * 8 + gr;
                bh[ni][0] = base[2 * ASZ + nb * GP + ks * 8 + tg];
                bh[ni][1] = base[2 * ASZ + nb * GP + ks * 8 + tg + 4];
            }
            #pragma unroll
            for (int mi = 0; mi < 2; mi++)
                #pragma unroll
                for (int ni = 0; ni < 4; ni++) {
                    mma8(acc[mi][ni], ah[mi], bh[ni][0], bh[ni][1]);
                    mma8(acc[mi][ni], al[mi], bh[ni][0], bh[ni][1]);
                }
        }

        if (more) s_store(sm + ((t + 1) & 1) * BUFW, tid, p);
        __syncthreads();
    }

    #pragma unroll
    for (int mi = 0; mi < 2; mi++) {
        const int r = row0 + warpM * 32 + mi * 16 + gr;
        #pragma unroll
        for (int ni = 0; ni < 4; ni++) {
            const int c = col0 + warpN * 32 + ni * 8 + tg * 2;
            const float bx = bias[c], by = bias[c + 1];
            float2 o0, o1;
            o0.x = acc[mi][ni][0] + bx;
            o0.y = acc[mi][ni][1] + by;
            o1.x = acc[mi][ni][2] + bx;
            o1.y = acc[mi][ni][3] + by;
            *(float2*)&C[(size_t)r * N + c] = o0;
            *(float2*)&C[(size_t)(r + 8) * N + c] = o1;
        }
    }
}

// ===========================================================================
// Flash attention with mma.sync tf32 (unchanged from R8 — passing, ~270us).
// ===========================================================================
#define AP 68
#define KT 64
#define ATT_SMEM_FLOATS (128 * AP + 8 * 16 * AP + 64)
#define ATT_SMEM_BYTES (ATT_SMEM_FLOATS * 4)

__global__ __launch_bounds__(256, 1)
void flash_mma(const float* __restrict__ qkv, const float* __restrict__ mask,
               float* __restrict__ att) {
    extern __shared__ float smf[];
    float* Ks = smf;                        // [j][d] pitch AP (64 rows)
    float* Vs = smf + 64 * AP;              // [d][j] pitch AP (64 rows)
    float* Pm = smf + 128 * AP;             // per-warp [16][AP]
    float* Lm = smf + 128 * AP + 8 * 16 * AP;

    const int it = (gridDim.x - 1) - blockIdx.x;   // heavy tiles first
    const int h  = blockIdx.y;
    const int b  = blockIdx.z;
    const int tid  = threadIdx.x;
    const int wid  = tid >> 5;
    const int lane = tid & 31;
    const int gr = lane >> 2, tg = lane & 3;
    const int i0 = it * 128 + wid * 16 + gr;       // thread's first q row
    float* Pw = Pm + wid * (16 * AP);

    // ---- Stage Q tile [128][64] into smf (pitch AP), then frags to regs ----
    {
        const float* qb = qkv + ((size_t)(b * Ss + it * 128) * 3) * Dd + h * HD;
        #pragma unroll
        for (int p = 0; p < 8; p++) {
            int g = p * 256 + tid;
            int r = g >> 4, c4 = g & 15;
            float4 v = *(const float4*)(qb + (size_t)r * 3072 + c4 * 4);
            *(float4*)&smf[r * AP + c4 * 4] = v;
        }
    }
    __syncthreads();
    unsigned qf[8][4];
    {
        const int rb = wid * 16 + gr;
        #pragma unroll
        for (int kb = 0; kb < 8; kb++) {
            qf[kb][0] = f2tf(smf[rb * AP + kb * 8 + tg]);
            qf[kb][1] = f2tf(smf[(rb + 8) * AP + kb * 8 + tg]);
            qf[kb][2] = f2tf(smf[rb * AP + kb * 8 + tg + 4]);
            qf[kb][3] = f2tf(smf[(rb + 8) * AP + kb * 8 + tg + 4]);
        }
    }

    float oacc[8][4];
    #pragma unroll
    for (int nb = 0; nb < 8; nb++)
        #pragma unroll
        for (int r = 0; r < 4; r++) oacc[nb][r] = 0.f;
    float m0 = -1e30f, m1 = -1e30f, l0 = 0.f, l1 = 0.f;

    const int ntiles = 2 * it + 2;

    for (int jt = 0; jt < ntiles; jt++) {
        const int j0 = jt * KT;
        __syncthreads();   // previous tile fully consumed
        // ---- K tile [j][d], tf32-rounded ----
        {
            const float* kb_ = qkv + ((size_t)(b * Ss + j0) * 3 + 1) * Dd + h * HD;
            #pragma unroll
            for (int p = 0; p < 4; p++) {
                int g = p * 256 + tid;
                int r = g >> 4, c4 = g & 15;
                float4 v = *(const float4*)(kb_ + (size_t)r * 3072 + c4 * 4);
                uint4 u;
                u.x = f2tf(v.x); u.y = f2tf(v.y);
                u.z = f2tf(v.z); u.w = f2tf(v.w);
                *(uint4*)&Ks[r * AP + c4 * 4] = u;
            }
        }
        // ---- V tile transposed: warp w owns d in [8w, 8w+8), ALL 64 j ----
        {
            const float* vb = qkv + ((size_t)(b * Ss + j0) * 3 + 2) * Dd + h * HD
                              + wid * 8;
            #pragma unroll
            for (int jh = 0; jh < 2; jh++) {
                const int j = jh * 32 + lane;
                float4 v0 = *(const float4*)(vb + (size_t)j * 3072);
                float4 v1 = *(const float4*)(vb + (size_t)j * 3072 + 4);
                const float* vf0 = &v0.x;
                const float* vf1 = &v1.x;
                #pragma unroll
                for (int ii = 0; ii < 4; ii++) {
                    Vs[(wid * 8 + ii) * AP + j] =
                        __uint_as_float(f2tf(vf0[ii]));
                    Vs[(wid * 8 + 4 + ii) * AP + j] =
                        __uint_as_float(f2tf(vf1[ii]));
                }
            }
        }
        if (tid < KT) Lm[tid] = __logf(mask[b * Ss + j0 + tid]);
        __syncthreads();

        // ---- S = Q K^T (64 MMAs) ----
        float sacc[8][4];
        #pragma unroll
        for (int nb = 0; nb < 8; nb++) {
            sacc[nb][0] = sacc[nb][1] = sacc[nb][2] = sacc[nb][3] = 0.f;
            #pragma unroll
            for (int kb = 0; kb < 8; kb++) {
                unsigned b0 = __float_as_uint(Ks[(nb * 8 + gr) * AP + kb * 8 + tg]);
                unsigned b1 = __float_as_uint(Ks[(nb * 8 + gr) * AP + kb * 8 + tg + 4]);
                mma8(sacc[nb], qf[kb], b0, b1);
            }
        }

        // ---- scale + logmask + causal ----
        const bool partial = (j0 + KT - 1 > i0);   // needs per-element mask
        #pragma unroll
        for (int nb = 0; nb < 8; nb++) {
            const int c = nb * 8 + 2 * tg;
            const float lmx = Lm[c], lmy = Lm[c + 1];
            sacc[nb][0] = sacc[nb][0] * 0.125f + lmx;
            sacc[nb][1] = sacc[nb][1] * 0.125f + lmy;
            sacc[nb][2] = sacc[nb][2] * 0.125f + lmx;
            sacc[nb][3] = sacc[nb][3] * 0.125f + lmy;
            if (partial) {
                const int jcx = j0 + c, jcy = j0 + c + 1;
                if (jcx > i0)     sacc[nb][0] = -1e30f;
                if (jcy > i0)     sacc[nb][1] = -1e30f;
                if (jcx > i0 + 8) sacc[nb][2] = -1e30f;
                if (jcy > i0 + 8) sacc[nb][3] = -1e30f;
            }
        }

        // ---- online softmax (rows i0, i0+8) ----
        float mx0 = -1e30f, mx1 = -1e30f;
        #pragma unroll
        for (int nb = 0; nb < 8; nb++) {
            mx0 = fmaxf(mx0, fmaxf(sacc[nb][0], sacc[nb][1]));
            mx1 = fmaxf(mx1, fmaxf(sacc[nb][2], sacc[nb][3]));
        }
        mx0 = fmaxf(mx0, __shfl_xor_sync(0xffffffffu, mx0, 1));
        mx0 = fmaxf(mx0, __shfl_xor_sync(0xffffffffu, mx0, 2));
        mx1 = fmaxf(mx1, __shfl_xor_sync(0xffffffffu, mx1, 1));
        mx1 = fmaxf(mx1, __shfl_xor_sync(0xffffffffu, mx1, 2));
        const float nm0 = fmaxf(m0, mx0), nm1 = fmaxf(m1, mx1);
        const float c0 = __expf(m0 - nm0), c1 = __expf(m1 - nm1);
        m0 = nm0; m1 = nm1;

        float ls0 = 0.f, ls1 = 0.f;
        #pragma unroll
        for (int nb = 0; nb < 8; nb++) {
            const float p0 = __expf(sacc[nb][0] - m0);
            const float p1 = __expf(sacc[nb][1] - m0);
            const float p2 = __expf(sacc[nb][2] - m1);
            const float p3 = __expf(sacc[nb][3] - m1);
            ls0 += p0 + p1;
            ls1 += p2 + p3;
            const int c = nb * 8 + 2 * tg;
            float2 w0, w1;
            w0.x = __uint_as_float(f2tf(p0));
            w0.y = __uint_as_float(f2tf(p1));
            w1.x = __uint_as_float(f2tf(p2));
            w1.y = __uint_as_float(f2tf(p3));
            *(float2*)&Pw[gr * AP + c] = w0;
            *(float2*)&Pw[(gr + 8) * AP + c] = w1;
        }
        ls0 += __shfl_xor_sync(0xffffffffu, ls0, 1);
        ls0 += __shfl_xor_sync(0xffffffffu, ls0, 2);
        ls1 += __shfl_xor_sync(0xffffffffu, ls1, 1);
        ls1 += __shfl_xor_sync(0xffffffffu, ls1, 2);
        l0 = l0 * c0 + ls0;
        l1 = l1 * c1 + ls1;
        #pragma unroll
        for (int nb = 0; nb < 8; nb++) {
            oacc[nb][0] *= c0; oacc[nb][1] *= c0;
            oacc[nb][2] *= c1; oacc[nb][3] *= c1;
        }
        __syncwarp();

        // ---- O += P V (64 MMAs) ----
        #pragma unroll
        for (int kb = 0; kb < 8; kb++) {
            unsigned af[4];
            af[0] = __float_as_uint(Pw[gr * AP + kb * 8 + tg]);
            af[1] = __float_as_uint(Pw[(gr + 8) * AP + kb * 8 + tg]);
            af[2] = __float_as_uint(Pw[gr * AP + kb * 8 + tg + 4]);
            af[3] = __float_as_uint(Pw[(gr + 8) * AP + kb * 8 + tg + 4]);
            #pragma unroll
            for (int nb = 0; nb < 8; nb++) {
                unsigned b0 = __float_as_uint(Vs[(nb * 8 + gr) * AP + kb * 8 + tg]);
                unsigned b1 = __float_as_uint(Vs[(nb * 8 + gr) * AP + kb * 8 + tg + 4]);
                mma8(oacc[nb], af, b0, b1);
            }
        }
    }

    // ---- epilogue ----
    const float inv0 = 1.f / l0, inv1 = 1.f / l1;
    float* out0 = att + (size_t)(b * Ss + i0) * Dd + h * HD;
    float* out1 = out0 + (size_t)8 * Dd;
    #pragma unroll
    for (int nb = 0; nb < 8; nb++) {
        const int c = nb * 8 + 2 * tg;
        float2 o0, o1;
        o0.x = oacc[nb][0] * inv0;
        o0.y = oacc[nb][1] * inv0;
        o1.x = oacc[nb][2] * inv1;
        o1.y = oacc[nb][3] * inv1;
        *(float2*)&out0[c] = o0;
        *(float2*)&out1[c] = o1;
    }
}

// ===========================================================================
// Launch
// ===========================================================================
extern "C" void kernel_launch(void* const* d_in, const int* in_sizes, int n_in,
                              void* d_out, int out_size) {
    const float* x     = (const float*)d_in[0];
    const float* mask  = (const float*)d_in[1];
    const float* W_qkv = (const float*)d_in[2];
    const float* b_qkv = (const float*)d_in[3];
    const float* W_o   = (const float*)d_in[4];
    const float* b_o   = (const float*)d_in[5];
    float* out = (float*)d_out;

    float* qkv_ptr = nullptr;
    float* att_ptr = nullptr;
    cudaGetSymbolAddress((void**)&qkv_ptr, g_qkv);
    cudaGetSymbolAddress((void**)&att_ptr, g_att);

    cudaFuncSetAttribute(gemm_mma, cudaFuncAttributeMaxDynamicSharedMemorySize,
                         GEMM_SMEM_BYTES);
    cudaFuncSetAttribute(flash_mma, cudaFuncAttributeMaxDynamicSharedMemorySize,
                         ATT_SMEM_BYTES);

    // 1) QKV projection
    gemm_mma<<<dim3(3 * Dd / 128, Mrows / 128), 512, GEMM_SMEM_BYTES>>>(
        x, W_qkv, b_qkv, qkv_ptr, Mrows, 3 * Dd, Dd);

    // 2) Flash attention (tensorized)
    flash_mma<<<dim3(Ss / 128, Hh, Bb), 256, ATT_SMEM_BYTES>>>(
        qkv_ptr, mask, att_ptr);

    // 3) Output projection
    gemm_mma<<<dim3(Dd / 128, Mrows / 128), 512, GEMM_SMEM_BYTES>>>(
        att_ptr, W_o, b_o, out, Mrows, Dd, Dd);
}